// round 11
// baseline (speedup 1.0000x reference)
#include <cuda_runtime.h>

// MemoryOnlyTitan — algebraic collapse of the reference:
// state0 == 0 -> write softmax uniform -> every memory slot = mean_t v
//             -> read softmax uniform  -> mem_out[b,t,:] = vbar[b,:] for all t
// vbar  = (sum_t c / T) @ Wv + bv          (c = [pm; x])
// row   = (LN(vbar)*gamma + beta) @ Wout + bout
// out[b,t,:] = row[b,:]  broadcast over all T = P+S tokens.
//
// 3 kernels:
//   k_sum   64MB read -> per-batch column sums (atomics), MLP-forced loads
//   k_mid   gemv + LN + gemv (4 blocks)
//   k_bcast 67MB streaming write + csum reset for the next graph replay

#define Bn   4
#define Sn   8192
#define Dn   512
#define Pn   32
#define Tn   (Pn + Sn)          // 8224
#define EPSf 1e-5f

#define XB      512             // x-sum blocks per batch
#define RP      (Sn / XB)       // 16 rows per block
#define D4      (Dn / 4)        // 128 float4 per row
#define N4      (Tn * D4)       // 1052672 float4 per batch

// scratch (allocation forbidden -> device globals; csum reset by k_bcast tail)
__device__ float g_csum[Bn * Dn];      // zero at start (static init / prev-run reset)
__device__ float g_outrow[Bn * Dn];

// ---------------------------------------------------------------------------
// Kernel 1: per-batch column sums of c = [pm; x] into g_csum via atomics.
// grid = (XB+1, Bn), block = 128. blockIdx.x < XB -> x slice; == XB -> pm.
// Loads are explicitly staged into v[8] (separate unrolled loop) to force
// ptxas to front-batch 8 independent LDG.128 before any FADD consumes them.
__global__ __launch_bounds__(128)
void k_sum(const float* __restrict__ x, const float* __restrict__ pm) {
    const int b  = blockIdx.y;
    const int t4 = threadIdx.x;                 // 0..127 (float4 column group)

    float4 acc = make_float4(0.f, 0.f, 0.f, 0.f);
    float4 v[8];

    if (blockIdx.x < XB) {
        const float4* __restrict__ src = reinterpret_cast<const float4*>(x)
            + (size_t)b * Sn * D4 + (size_t)blockIdx.x * RP * D4 + t4;
#pragma unroll
        for (int r = 0; r < RP / 8; ++r) {
#pragma unroll
            for (int i = 0; i < 8; ++i) v[i] = __ldcs(&src[(size_t)(r * 8 + i) * D4]);
#pragma unroll
            for (int i = 0; i < 8; ++i) {
                acc.x += v[i].x; acc.y += v[i].y; acc.z += v[i].z; acc.w += v[i].w;
            }
        }
    } else {
        const float4* __restrict__ src = reinterpret_cast<const float4*>(pm) + t4;
#pragma unroll
        for (int r = 0; r < Pn / 8; ++r) {
#pragma unroll
            for (int i = 0; i < 8; ++i) v[i] = __ldcs(&src[(size_t)(r * 8 + i) * D4]);
#pragma unroll
            for (int i = 0; i < 8; ++i) {
                acc.x += v[i].x; acc.y += v[i].y; acc.z += v[i].z; acc.w += v[i].w;
            }
        }
    }
    float* dst = &g_csum[b * Dn + t4 * 4];
    atomicAdd(dst + 0, acc.x);
    atomicAdd(dst + 1, acc.y);
    atomicAdd(dst + 2, acc.z);
    atomicAdd(dst + 3, acc.w);
}

// ---------------------------------------------------------------------------
// Kernel 2: fused middle stage, one block per batch, 512 threads.
//   vbar = csum/T @ Wv + bv ; normed = LN(vbar)*gamma + beta ;
//   outrow = normed @ Wout + bout
// Thread layout: p = tid/128 (K-split part), j = tid%128 (float4 d-group).
__global__ __launch_bounds__(512, 1)
void k_mid(const float* __restrict__ Wv,  const float* __restrict__ bv,
           const float* __restrict__ gamma, const float* __restrict__ beta,
           const float* __restrict__ Wout, const float* __restrict__ bout) {
    __shared__ float  act[Dn];          // activation vector (csum/T, then normed)
    __shared__ float4 part[4][D4];      // K-split partials
    __shared__ float  red[16];
    __shared__ float  bc[2];

    const int b   = blockIdx.x;
    const int tid = threadIdx.x;
    const int p   = tid >> 7;           // 0..3
    const int j   = tid & 127;          // 0..127
    const int e0  = p * 128;

    act[tid] = g_csum[b * Dn + tid] * (1.f / (float)Tn);
    __syncthreads();

    // ---- GEMV 1: vbar4[j] = sum_e act[e] * Wv[e][4j..4j+3] ----
    const float4* __restrict__ Wv4 = reinterpret_cast<const float4*>(Wv);
    float4 a = make_float4(0.f, 0.f, 0.f, 0.f);
#pragma unroll 8
    for (int e = 0; e < 128; ++e) {
        const float  c = act[e0 + e];
        const float4 w = Wv4[(size_t)(e0 + e) * D4 + j];
        a.x += c * w.x; a.y += c * w.y; a.z += c * w.z; a.w += c * w.w;
    }
    part[p][j] = a;
    __syncthreads();

    float4 vb = make_float4(0.f, 0.f, 0.f, 0.f);
    if (p == 0) {
        const float4 bv4 = reinterpret_cast<const float4*>(bv)[j];
        float4 q0 = part[0][j], q1 = part[1][j], q2 = part[2][j], q3 = part[3][j];
        vb.x = q0.x + q1.x + q2.x + q3.x + bv4.x;
        vb.y = q0.y + q1.y + q2.y + q3.y + bv4.y;
        vb.z = q0.z + q1.z + q2.z + q3.z + bv4.z;
        vb.w = q0.w + q1.w + q2.w + q3.w + bv4.w;
    }

    // ---- LayerNorm (values live in threads p==0 as float4) ----
    float s = (p == 0) ? (vb.x + vb.y + vb.z + vb.w) : 0.f;
#pragma unroll
    for (int o = 16; o; o >>= 1) s += __shfl_xor_sync(0xffffffffu, s, o);
    if ((tid & 31) == 0) red[tid >> 5] = s;
    __syncthreads();
    if (tid == 0) {
        float t = 0.f;
#pragma unroll
        for (int i = 0; i < 16; ++i) t += red[i];
        bc[0] = t * (1.f / (float)Dn);
    }
    __syncthreads();
    const float mu = bc[0];

    float4 df = make_float4(vb.x - mu, vb.y - mu, vb.z - mu, vb.w - mu);
    float q = (p == 0) ? (df.x * df.x + df.y * df.y + df.z * df.z + df.w * df.w) : 0.f;
#pragma unroll
    for (int o = 16; o; o >>= 1) q += __shfl_xor_sync(0xffffffffu, q, o);
    if ((tid & 31) == 0) red[tid >> 5] = q;
    __syncthreads();
    if (tid == 0) {
        float t = 0.f;
#pragma unroll
        for (int i = 0; i < 16; ++i) t += red[i];
        bc[1] = rsqrtf(t * (1.f / (float)Dn) + EPSf);
    }
    __syncthreads();
    const float rstd = bc[1];

    if (p == 0) {
        const float4 g4 = reinterpret_cast<const float4*>(gamma)[j];
        const float4 b4 = reinterpret_cast<const float4*>(beta)[j];
        act[j * 4 + 0] = df.x * rstd * g4.x + b4.x;
        act[j * 4 + 1] = df.y * rstd * g4.y + b4.y;
        act[j * 4 + 2] = df.z * rstd * g4.z + b4.z;
        act[j * 4 + 3] = df.w * rstd * g4.w + b4.w;
    }
    __syncthreads();

    // ---- GEMV 2: outrow4[j] = sum_e act[e] * Wout[e][4j..4j+3] + bout ----
    const float4* __restrict__ Wo4 = reinterpret_cast<const float4*>(Wout);
    float4 a2 = make_float4(0.f, 0.f, 0.f, 0.f);
#pragma unroll 8
    for (int e = 0; e < 128; ++e) {
        const float  c = act[e0 + e];
        const float4 w = Wo4[(size_t)(e0 + e) * D4 + j];
        a2.x += c * w.x; a2.y += c * w.y; a2.z += c * w.z; a2.w += c * w.w;
    }
    part[p][j] = a2;
    __syncthreads();

    if (p == 0) {
        const float4 bo4 = reinterpret_cast<const float4*>(bout)[j];
        float4 q0 = part[0][j], q1 = part[1][j], q2 = part[2][j], q3 = part[3][j];
        float4 o;
        o.x = q0.x + q1.x + q2.x + q3.x + bo4.x;
        o.y = q0.y + q1.y + q2.y + q3.y + bo4.y;
        o.z = q0.z + q1.z + q2.z + q3.z + bo4.z;
        o.w = q0.w + q1.w + q2.w + q3.w + bo4.w;
        reinterpret_cast<float4*>(g_outrow)[b * D4 + j] = o;
    }
}

// ---------------------------------------------------------------------------
// Kernel 3: broadcast outrow[b,:] to all Tn tokens (67 MB coalesced streaming
// stores, evict-first), and reset g_csum for the next graph replay (csum was
// fully consumed by k_mid, which precedes this kernel in stream order).
__global__ __launch_bounds__(256)
void k_bcast(float4* __restrict__ out) {
    __shared__ float4 row[D4];
    const int b = blockIdx.y;
    if (threadIdx.x < D4)
        row[threadIdx.x] = reinterpret_cast<const float4*>(g_outrow)[b * D4 + threadIdx.x];
    __syncthreads();

    const unsigned base = blockIdx.x * 2048u + threadIdx.x;
    const float4 val = row[threadIdx.x & (D4 - 1)];   // 256 % 128 == 0 keeps col fixed
    float4* __restrict__ ob = out + (size_t)b * N4;
#pragma unroll
    for (int j = 0; j < 8; ++j) __stcs(&ob[base + j * 256u], val);

    if (blockIdx.x == 0) {                            // accumulator reset for next run
        g_csum[b * Dn + threadIdx.x]       = 0.f;
        g_csum[b * Dn + threadIdx.x + 256] = 0.f;
    }
}

// ---------------------------------------------------------------------------
extern "C" void kernel_launch(void* const* d_in, const int* in_sizes, int n_in,
                              void* d_out, int out_size) {
    const float* x     = (const float*)d_in[0];
    const float* pm    = (const float*)d_in[1];
    // d_in[2] Wk, d_in[3] bk, d_in[6] Wq, d_in[7] bq -- unused (zero-state algebra)
    const float* Wv    = (const float*)d_in[4];
    const float* bv    = (const float*)d_in[5];
    const float* gamma = (const float*)d_in[8];
    const float* beta  = (const float*)d_in[9];
    const float* Wout  = (const float*)d_in[10];
    const float* bout  = (const float*)d_in[11];

    k_sum  <<<dim3(XB + 1, Bn), 128>>>(x, pm);
    k_mid  <<<Bn, 512>>>(Wv, bv, gamma, beta, Wout, bout);
    k_bcast<<<dim3(N4 / (256 * 8), Bn), 256>>>((float4*)d_out);
}

// round 13
// speedup vs baseline: 1.1474x; 1.1474x over previous
#include <cuda_runtime.h>

// MemoryOnlyTitan — algebraic collapse of the reference:
// state0 == 0 -> write softmax uniform -> every memory slot = mean_t v
//             -> read softmax uniform  -> mem_out[b,t,:] = vbar[b,:] for all t
// vbar  = (sum_t c / T) @ Wv + bv          (c = [pm; x])
// row   = (LN(vbar)*gamma + beta) @ Wout + bout
// out[b,t,:] = row[b,:]  broadcast over all T = P+S tokens.
//
// 3 kernels:
//   k_sum   64MB read -> per-batch column sums (8 independent acc chains -> MLP)
//   k_mid   gemv + LN + gemv (4 blocks)
//   k_bcast 67MB streaming write (__stcs) + csum reset for the next graph replay

#define Bn   4
#define Sn   8192
#define Dn   512
#define Pn   32
#define Tn   (Pn + Sn)          // 8224
#define EPSf 1e-5f

#define XB      256             // x-sum blocks per batch
#define RP      (Sn / XB)       // 32 rows per block (== Pn, so pm block reuses loop)
#define D4      (Dn / 4)        // 128 float4 per row
#define N4      (Tn * D4)       // 1052672 float4 per batch

// scratch (allocation forbidden -> device globals; csum reset by k_bcast tail)
__device__ float g_csum[Bn * Dn];      // zero at start (static init / prev-run reset)
__device__ float g_outrow[Bn * Dn];

// ---------------------------------------------------------------------------
// Kernel 1: per-batch column sums of c = [pm; x] into g_csum via atomics.
// grid = (XB+1, Bn), block = 128. blockIdx.x < XB -> x slice; == XB -> pm.
// 8 independent accumulator chains let ptxas front-batch 8 LDG.128 per warp
// (MLP ~8) instead of the serialized load->add chain that regs=32 forces.
__global__ __launch_bounds__(128)
void k_sum(const float* __restrict__ x, const float* __restrict__ pm) {
    const int b  = blockIdx.y;
    const int t4 = threadIdx.x;                 // 0..127 (float4 column group)

    const float4* __restrict__ src =
        (blockIdx.x < XB)
            ? reinterpret_cast<const float4*>(x)
                  + (size_t)b * Sn * D4 + (size_t)blockIdx.x * RP * D4 + t4
            : reinterpret_cast<const float4*>(pm) + t4;

    float4 acc[8];
#pragma unroll
    for (int i = 0; i < 8; ++i) acc[i] = make_float4(0.f, 0.f, 0.f, 0.f);

#pragma unroll
    for (int r = 0; r < RP / 8; ++r) {          // 4 iterations of 8 rows
#pragma unroll
        for (int i = 0; i < 8; ++i) {           // 8 independent chains
            float4 v = src[(size_t)(r * 8 + i) * D4];
            acc[i].x += v.x; acc[i].y += v.y; acc[i].z += v.z; acc[i].w += v.w;
        }
    }

    // tree-merge the 8 chains
#pragma unroll
    for (int s = 4; s; s >>= 1)
#pragma unroll
        for (int i = 0; i < s; ++i) {
            acc[i].x += acc[i + s].x; acc[i].y += acc[i + s].y;
            acc[i].z += acc[i + s].z; acc[i].w += acc[i + s].w;
        }

    float* dst = &g_csum[b * Dn + t4 * 4];
    atomicAdd(dst + 0, acc[0].x);
    atomicAdd(dst + 1, acc[0].y);
    atomicAdd(dst + 2, acc[0].z);
    atomicAdd(dst + 3, acc[0].w);
}

// ---------------------------------------------------------------------------
// Kernel 2: fused middle stage, one block per batch, 512 threads.
//   vbar = csum/T @ Wv + bv ; normed = LN(vbar)*gamma + beta ;
//   outrow = normed @ Wout + bout
// Thread layout: p = tid/128 (K-split part), j = tid%128 (float4 d-group).
__global__ __launch_bounds__(512, 1)
void k_mid(const float* __restrict__ Wv,  const float* __restrict__ bv,
           const float* __restrict__ gamma, const float* __restrict__ beta,
           const float* __restrict__ Wout, const float* __restrict__ bout) {
    __shared__ float  act[Dn];          // activation vector (csum/T, then normed)
    __shared__ float4 part[4][D4];      // K-split partials
    __shared__ float  red[16];
    __shared__ float  bc[2];

    const int b   = blockIdx.x;
    const int tid = threadIdx.x;
    const int p   = tid >> 7;           // 0..3
    const int j   = tid & 127;          // 0..127
    const int e0  = p * 128;

    act[tid] = g_csum[b * Dn + tid] * (1.f / (float)Tn);
    __syncthreads();

    // ---- GEMV 1: vbar4[j] = sum_e act[e] * Wv[e][4j..4j+3] ----
    const float4* __restrict__ Wv4 = reinterpret_cast<const float4*>(Wv);
    float4 a = make_float4(0.f, 0.f, 0.f, 0.f);
#pragma unroll 8
    for (int e = 0; e < 128; ++e) {
        const float  c = act[e0 + e];
        const float4 w = Wv4[(size_t)(e0 + e) * D4 + j];
        a.x += c * w.x; a.y += c * w.y; a.z += c * w.z; a.w += c * w.w;
    }
    part[p][j] = a;
    __syncthreads();

    float4 vb = make_float4(0.f, 0.f, 0.f, 0.f);
    if (p == 0) {
        const float4 bv4 = reinterpret_cast<const float4*>(bv)[j];
        float4 q0 = part[0][j], q1 = part[1][j], q2 = part[2][j], q3 = part[3][j];
        vb.x = q0.x + q1.x + q2.x + q3.x + bv4.x;
        vb.y = q0.y + q1.y + q2.y + q3.y + bv4.y;
        vb.z = q0.z + q1.z + q2.z + q3.z + bv4.z;
        vb.w = q0.w + q1.w + q2.w + q3.w + bv4.w;
    }

    // ---- LayerNorm (values live in threads p==0 as float4) ----
    float s = (p == 0) ? (vb.x + vb.y + vb.z + vb.w) : 0.f;
#pragma unroll
    for (int o = 16; o; o >>= 1) s += __shfl_xor_sync(0xffffffffu, s, o);
    if ((tid & 31) == 0) red[tid >> 5] = s;
    __syncthreads();
    if (tid == 0) {
        float t = 0.f;
#pragma unroll
        for (int i = 0; i < 16; ++i) t += red[i];
        bc[0] = t * (1.f / (float)Dn);
    }
    __syncthreads();
    const float mu = bc[0];

    float4 df = make_float4(vb.x - mu, vb.y - mu, vb.z - mu, vb.w - mu);
    float q = (p == 0) ? (df.x * df.x + df.y * df.y + df.z * df.z + df.w * df.w) : 0.f;
#pragma unroll
    for (int o = 16; o; o >>= 1) q += __shfl_xor_sync(0xffffffffu, q, o);
    if ((tid & 31) == 0) red[tid >> 5] = q;
    __syncthreads();
    if (tid == 0) {
        float t = 0.f;
#pragma unroll
        for (int i = 0; i < 16; ++i) t += red[i];
        bc[1] = rsqrtf(t * (1.f / (float)Dn) + EPSf);
    }
    __syncthreads();
    const float rstd = bc[1];

    if (p == 0) {
        const float4 g4 = reinterpret_cast<const float4*>(gamma)[j];
        const float4 b4 = reinterpret_cast<const float4*>(beta)[j];
        act[j * 4 + 0] = df.x * rstd * g4.x + b4.x;
        act[j * 4 + 1] = df.y * rstd * g4.y + b4.y;
        act[j * 4 + 2] = df.z * rstd * g4.z + b4.z;
        act[j * 4 + 3] = df.w * rstd * g4.w + b4.w;
    }
    __syncthreads();

    // ---- GEMV 2: outrow4[j] = sum_e act[e] * Wout[e][4j..4j+3] + bout ----
    const float4* __restrict__ Wo4 = reinterpret_cast<const float4*>(Wout);
    float4 a2 = make_float4(0.f, 0.f, 0.f, 0.f);
#pragma unroll 8
    for (int e = 0; e < 128; ++e) {
        const float  c = act[e0 + e];
        const float4 w = Wo4[(size_t)(e0 + e) * D4 + j];
        a2.x += c * w.x; a2.y += c * w.y; a2.z += c * w.z; a2.w += c * w.w;
    }
    part[p][j] = a2;
    __syncthreads();

    if (p == 0) {
        const float4 bo4 = reinterpret_cast<const float4*>(bout)[j];
        float4 q0 = part[0][j], q1 = part[1][j], q2 = part[2][j], q3 = part[3][j];
        float4 o;
        o.x = q0.x + q1.x + q2.x + q3.x + bo4.x;
        o.y = q0.y + q1.y + q2.y + q3.y + bo4.y;
        o.z = q0.z + q1.z + q2.z + q3.z + bo4.z;
        o.w = q0.w + q1.w + q2.w + q3.w + bo4.w;
        reinterpret_cast<float4*>(g_outrow)[b * D4 + j] = o;
    }
}

// ---------------------------------------------------------------------------
// Kernel 3: broadcast outrow[b,:] to all Tn tokens (67 MB coalesced streaming
// stores, evict-first — measured ~16us faster than default stores), and reset
// g_csum for the next graph replay (csum fully consumed by k_mid above).
__global__ __launch_bounds__(256)
void k_bcast(float4* __restrict__ out) {
    __shared__ float4 row[D4];
    const int b = blockIdx.y;
    if (threadIdx.x < D4)
        row[threadIdx.x] = reinterpret_cast<const float4*>(g_outrow)[b * D4 + threadIdx.x];
    __syncthreads();

    const unsigned base = blockIdx.x * 2048u + threadIdx.x;
    const float4 val = row[threadIdx.x & (D4 - 1)];   // 256 % 128 == 0 keeps col fixed
    float4* __restrict__ ob = out + (size_t)b * N4;
#pragma unroll
    for (int j = 0; j < 8; ++j) __stcs(&ob[base + j * 256u], val);

    if (blockIdx.x == 0) {                            // accumulator reset for next run
        g_csum[b * Dn + threadIdx.x]       = 0.f;
        g_csum[b * Dn + threadIdx.x + 256] = 0.f;
    }
}

// ---------------------------------------------------------------------------
extern "C" void kernel_launch(void* const* d_in, const int* in_sizes, int n_in,
                              void* d_out, int out_size) {
    const float* x     = (const float*)d_in[0];
    const float* pm    = (const float*)d_in[1];
    // d_in[2] Wk, d_in[3] bk, d_in[6] Wq, d_in[7] bq -- unused (zero-state algebra)
    const float* Wv    = (const float*)d_in[4];
    const float* bv    = (const float*)d_in[5];
    const float* gamma = (const float*)d_in[8];
    const float* beta  = (const float*)d_in[9];
    const float* Wout  = (const float*)d_in[10];
    const float* bout  = (const float*)d_in[11];

    k_sum  <<<dim3(XB + 1, Bn), 128>>>(x, pm);
    k_mid  <<<Bn, 512>>>(Wv, bv, gamma, beta, Wout, bout);
    k_bcast<<<dim3(N4 / (256 * 8), Bn), 256>>>((float4*)d_out);
}

// round 15
// speedup vs baseline: 1.3233x; 1.1533x over previous
#include <cuda_runtime.h>

// MemoryOnlyTitan — algebraic collapse of the reference:
// state0 == 0 -> write softmax uniform -> every memory slot = mean_t v
//             -> read softmax uniform  -> mem_out[b,t,:] = vbar[b,:] for all t
// vbar  = (sum_t c / T) @ Wv + bv          (c = [pm; x])
// row   = (LN(vbar)*gamma + beta) @ Wout + bout
// out[b,t,:] = row[b,:]  broadcast over all T = P+S tokens.
//
// 5 kernels (graph-replay gaps measured ~free):
//   k_sum   64MB read, 512-thr blocks for occupancy-driven latency hiding
//   k_gemv  x2: 32 blocks, batch-shared weight read (W read exactly once)
//   k_ln    LayerNorm (adds bv)
//   k_bcast 67MB streaming write (__stcs), adds bout, resets csum

#define Bn   4
#define Sn   8192
#define Dn   512
#define Pn   32
#define Tn   (Pn + Sn)          // 8224
#define EPSf 1e-5f

#define XB      256             // x-sum blocks per batch
#define RPB     32              // rows per block (== Pn, pm block reuses loop)
#define D4      (Dn / 4)        // 128 float4 per row
#define N4      (Tn * D4)       // 1052672 float4 per batch
#define EB      16              // e-rows per gemv block -> 32 blocks

// scratch (allocation forbidden -> device globals)
// g_csum  : accumulated by k_sum, zeroed by k_bcast tail (next-replay clean)
// g_vbar  : accumulated by k_gemv(0), zeroed by k_sum pm-blocks
// g_outrow: accumulated by k_gemv(1), zeroed by k_sum pm-blocks
__device__ float g_csum[Bn * Dn];
__device__ float g_vbar[Bn * Dn];
__device__ float g_normed[Bn * Dn];
__device__ float g_outrow[Bn * Dn];

// ---------------------------------------------------------------------------
// Kernel 1: per-batch column sums of c = [pm; x] into g_csum via atomics.
// grid = (XB+1, Bn), block = 512 (4 row-lanes x 128 float4-cols).
// 16.4K warps total -> ~full occupancy; latency hidden by warp count, not
// per-thread MLP (ptxas register-minimizes any staging attempt anyway).
__global__ __launch_bounds__(512)
void k_sum(const float* __restrict__ x, const float* __restrict__ pm) {
    __shared__ float4 sred[4][D4];              // 8KB lane-reduce buffer
    const int b    = blockIdx.y;
    const int tid  = threadIdx.x;
    const int j4   = tid & 127;                 // float4 column group
    const int lane = tid >> 7;                  // 0..3 row-lane
    const bool isPm = (blockIdx.x == XB);

    const float4* __restrict__ src = isPm
        ? reinterpret_cast<const float4*>(pm) + (size_t)(lane * 8) * D4 + j4
        : reinterpret_cast<const float4*>(x)
              + (size_t)b * Sn * D4
              + (size_t)(blockIdx.x * RPB + lane * 8) * D4 + j4;

    float4 acc = make_float4(0.f, 0.f, 0.f, 0.f);
#pragma unroll
    for (int r = 0; r < 8; ++r) {
        float4 v = src[(size_t)r * D4];
        acc.x += v.x; acc.y += v.y; acc.z += v.z; acc.w += v.w;
    }
    sred[lane][j4] = acc;
    __syncthreads();

    if (lane == 0) {
        float4 a0 = sred[0][j4], a1 = sred[1][j4], a2 = sred[2][j4], a3 = sred[3][j4];
        float* dst = &g_csum[b * Dn + j4 * 4];
        atomicAdd(dst + 0, a0.x + a1.x + a2.x + a3.x);
        atomicAdd(dst + 1, a0.y + a1.y + a2.y + a3.y);
        atomicAdd(dst + 2, a0.z + a1.z + a2.z + a3.z);
        atomicAdd(dst + 3, a0.w + a1.w + a2.w + a3.w);
    }

    // pm blocks also reset the downstream accumulators for this replay
    // (g_vbar / g_outrow are only accumulated by later kernels; no race here).
    if (isPm) {
        if (lane == 1) {
            float* p = &g_vbar[b * Dn + j4 * 4];
            p[0] = 0.f; p[1] = 0.f; p[2] = 0.f; p[3] = 0.f;
        } else if (lane == 2) {
            float* p = &g_outrow[b * Dn + j4 * 4];
            p[0] = 0.f; p[1] = 0.f; p[2] = 0.f; p[3] = 0.f;
        }
    }
}

// ---------------------------------------------------------------------------
// Kernel 2/4: batch-shared GEMV. grid = 32 (e-chunks of EB=16), block = 512.
// Each block reads its 16x512 weight slice EXACTLY ONCE and applies it to all
// 4 batch activation rows. mode 0: vbar += (csum/T)@Wv ; 1: outrow += normed@Wout.
__global__ __launch_bounds__(512)
void k_gemv(const float* __restrict__ W, int mode) {
    __shared__ float  sact[Bn][EB];
    __shared__ float4 spart[4][Bn][D4];         // [r][b][j4], 32KB
    const int tid = threadIdx.x;
    const int j4  = tid & 127;
    const int r   = tid >> 7;                   // 0..3 (covers 4 e-rows each)
    const int e0  = blockIdx.x * EB;

    const float* src = mode ? g_normed : g_csum;
    float*       dst = mode ? g_outrow : g_vbar;
    const float  scale = mode ? 1.f : (1.f / (float)Tn);

    if (tid < Bn * EB)
        sact[tid >> 4][tid & 15] = src[(tid >> 4) * Dn + e0 + (tid & 15)] * scale;
    __syncthreads();

    const float4* __restrict__ W4 = reinterpret_cast<const float4*>(W);
    float4 acc[Bn];
#pragma unroll
    for (int b = 0; b < Bn; ++b) acc[b] = make_float4(0.f, 0.f, 0.f, 0.f);

#pragma unroll
    for (int i = 0; i < EB / 4; ++i) {          // 4 e-rows per r-lane
        const int el = r * 4 + i;
        const float4 w = W4[(size_t)(e0 + el) * D4 + j4];
#pragma unroll
        for (int b = 0; b < Bn; ++b) {
            const float c = sact[b][el];
            acc[b].x += c * w.x; acc[b].y += c * w.y;
            acc[b].z += c * w.z; acc[b].w += c * w.w;
        }
    }
#pragma unroll
    for (int b = 0; b < Bn; ++b) spart[r][b][j4] = acc[b];
    __syncthreads();

    // thread handles batch b = r, column j4: reduce over the 4 r-lanes
    float4 s0 = spart[0][r][j4], s1 = spart[1][r][j4];
    float4 s2 = spart[2][r][j4], s3 = spart[3][r][j4];
    float* dp = &dst[r * Dn + j4 * 4];
    atomicAdd(dp + 0, s0.x + s1.x + s2.x + s3.x);
    atomicAdd(dp + 1, s0.y + s1.y + s2.y + s3.y);
    atomicAdd(dp + 2, s0.z + s1.z + s2.z + s3.z);
    atomicAdd(dp + 3, s0.w + s1.w + s2.w + s3.w);
}

// ---------------------------------------------------------------------------
// Kernel 3: per-batch LayerNorm of (vbar + bv) -> normed. grid = Bn, block = 512.
__global__ __launch_bounds__(512)
void k_ln(const float* __restrict__ bv, const float* __restrict__ gamma,
          const float* __restrict__ beta) {
    __shared__ float red[16];
    __shared__ float bc[2];
    const int b = blockIdx.x;
    const int d = threadIdx.x;

    const float v = g_vbar[b * Dn + d] + bv[d];

    float s = v;
#pragma unroll
    for (int o = 16; o; o >>= 1) s += __shfl_xor_sync(0xffffffffu, s, o);
    if ((d & 31) == 0) red[d >> 5] = s;
    __syncthreads();
    if (d == 0) {
        float t = 0.f;
#pragma unroll
        for (int i = 0; i < 16; ++i) t += red[i];
        bc[0] = t * (1.f / (float)Dn);
    }
    __syncthreads();
    const float mu   = bc[0];
    const float diff = v - mu;

    float q = diff * diff;
#pragma unroll
    for (int o = 16; o; o >>= 1) q += __shfl_xor_sync(0xffffffffu, q, o);
    if ((d & 31) == 0) red[d >> 5] = q;
    __syncthreads();
    if (d == 0) {
        float t = 0.f;
#pragma unroll
        for (int i = 0; i < 16; ++i) t += red[i];
        bc[1] = rsqrtf(t * (1.f / (float)Dn) + EPSf);
    }
    __syncthreads();

    g_normed[b * Dn + d] = diff * bc[1] * gamma[d] + beta[d];
}

// ---------------------------------------------------------------------------
// Kernel 5: broadcast (outrow + bout) to all Tn tokens. 67MB coalesced
// streaming stores (evict-first). Resets g_csum for the next graph replay
// (csum was fully consumed by k_gemv(0) earlier in this replay).
__global__ __launch_bounds__(256)
void k_bcast(float4* __restrict__ out, const float* __restrict__ bout) {
    __shared__ float4 row[D4];
    const int b = blockIdx.y;
    if (threadIdx.x < D4) {
        float4 o  = reinterpret_cast<const float4*>(g_outrow)[b * D4 + threadIdx.x];
        float4 bo = reinterpret_cast<const float4*>(bout)[threadIdx.x];
        o.x += bo.x; o.y += bo.y; o.z += bo.z; o.w += bo.w;
        row[threadIdx.x] = o;
    }
    __syncthreads();

    const unsigned base = blockIdx.x * 2048u + threadIdx.x;
    const float4 val = row[threadIdx.x & (D4 - 1)];   // 256 % 128 == 0: col fixed
    float4* __restrict__ ob = out + (size_t)b * N4;
#pragma unroll
    for (int j = 0; j < 8; ++j) __stcs(&ob[base + j * 256u], val);

    if (blockIdx.x == 0) {                            // accumulator reset
        g_csum[b * Dn + threadIdx.x]       = 0.f;
        g_csum[b * Dn + threadIdx.x + 256] = 0.f;
    }
}

// ---------------------------------------------------------------------------
extern "C" void kernel_launch(void* const* d_in, const int* in_sizes, int n_in,
                              void* d_out, int out_size) {
    const float* x     = (const float*)d_in[0];
    const float* pm    = (const float*)d_in[1];
    // d_in[2] Wk, d_in[3] bk, d_in[6] Wq, d_in[7] bq -- unused (zero-state algebra)
    const float* Wv    = (const float*)d_in[4];
    const float* bv    = (const float*)d_in[5];
    const float* gamma = (const float*)d_in[8];
    const float* beta  = (const float*)d_in[9];
    const float* Wout  = (const float*)d_in[10];
    const float* bout  = (const float*)d_in[11];

    k_sum  <<<dim3(XB + 1, Bn), 512>>>(x, pm);
    k_gemv <<<Dn / EB, 512>>>(Wv, 0);
    k_ln   <<<Bn, 512>>>(bv, gamma, beta);
    k_gemv <<<Dn / EB, 512>>>(Wout, 1);
    k_bcast<<<dim3(N4 / (256 * 8), Bn), 256>>>((float4*)d_out, bout);
}